// round 15
// baseline (speedup 1.0000x reference)
#include <cuda_runtime.h>

#define Hh 256
#define Ww 704
#define HW (Hh*Ww)      // 180224
#define W4 (Ww/4)       // 176
#define CIMG 256
#define COUTC 131
#define GRID_BLOCKS 444

// Scratch (device globals; no allocation allowed)
__device__ float4 d_gpart4[8 * (HW/4)];   // 8 channel-slab partial sums of gated
__device__ float d_spt[HW];
__device__ float4 d_att4[HW/4];
__device__ float d_v2[9*COUTC];
__device__ float d_u0[9*35];
__device__ float d_u1[9*67];
__device__ float d_wg[9];
__device__ float d_K[9];
__device__ unsigned int d_cnt = 0;        // barrier arrivals (self-resetting)
__device__ unsigned int d_gen = 0;        // barrier generation (monotonic)

// ---------------------------------------------------------------------------
// Grid-wide barrier: sense-reversal on generation counter. Replay-safe: spin
// compares against the locally captured generation, counter resets to 0 at
// every barrier, so state is clean for the next graph replay.
// ---------------------------------------------------------------------------
__device__ __forceinline__ void grid_sync() {
    __syncthreads();
    if (threadIdx.x == 0) {
        unsigned int g = *(volatile unsigned int*)&d_gen;
        __threadfence();
        if (atomicAdd(&d_cnt, 1u) == GRID_BLOCKS - 1u) {
            atomicExch(&d_cnt, 0u);
            __threadfence();
            atomicAdd(&d_gen, 1u);
        } else {
            while (*(volatile unsigned int*)&d_gen == g) { __nanosleep(64); }
        }
        __threadfence();
    }
    __syncthreads();
}

// ---------------------------------------------------------------------------
// Phase 0a: per-tap weight fold (9 virtual blocks, 256 threads each).
// ---------------------------------------------------------------------------
__device__ void fold_part(int t,
                          const float* __restrict__ sp_w,
                          const float* __restrict__ rd0_w,
                          const float* __restrict__ rd1_w,
                          const float* __restrict__ rd0_b,
                          const float* __restrict__ rd1_b,
                          const float* __restrict__ rd2_w,
                          const float* __restrict__ rd2_b,
                          const float* __restrict__ rd3_b) {
    __shared__ float spcol[COUTC];
    __shared__ float v2row[COUTC];
    int tid = threadIdx.x;
    __syncthreads();
    if (tid < COUTC) spcol[tid] = sp_w[tid * 9 + t];
    __syncthreads();
    if (tid < COUTC) {
        float a = 0.f;
        #pragma unroll 4
        for (int c = 0; c < COUTC; ++c) a += spcol[c] * rd2_w[c * COUTC + tid];
        v2row[tid] = a;
        d_v2[t * COUTC + tid] = a;
    }
    __syncthreads();
    if (tid < 35) {
        float a = 0.f;
        #pragma unroll 4
        for (int j = 0; j < COUTC; ++j) a += v2row[j] * rd0_w[j * 35 + tid];
        d_u0[t * 35 + tid] = a;
    } else if (tid >= 64 && tid < 64 + 67) {
        int i = tid - 64;
        float a = 0.f;
        #pragma unroll 4
        for (int j = 0; j < COUTC; ++j) a += v2row[j] * rd1_w[j * 67 + i];
        d_u1[t * 67 + i] = a;
    } else if (tid == 192) {
        float w = 0.f, k = 0.f;
        #pragma unroll 4
        for (int c = 0; c < COUTC; ++c) {
            w += spcol[c];
            k += v2row[c] * (rd0_b[c] + rd1_b[c]) + spcol[c] * rd2_b[c];
        }
        d_wg[t] = w;
        d_K[t]  = k + w * rd3_b[0];
    }
}

// ---------------------------------------------------------------------------
// Phase 1a: gated slab (virtual block b of 1408 = 176 pixel x 8 slabs).
// ---------------------------------------------------------------------------
__device__ void gated_part(const float* __restrict__ img,
                           const float* __restrict__ rd3_w, int b) {
    __shared__ float sw[32];
    int pb = b % 176, cb = b / 176;
    int c0 = cb * 32;
    __syncthreads();
    if (threadIdx.x < 32) sw[threadIdx.x] = rd3_w[c0 + threadIdx.x];
    __syncthreads();
    int p4 = pb * 256 + threadIdx.x;
    const float4* base = (const float4*)img + (size_t)c0 * (HW/4) + p4;
    float4 acc = make_float4(0.f, 0.f, 0.f, 0.f);
    #pragma unroll
    for (int c = 0; c < 32; ++c) {
        float w = sw[c];
        float4 x = __ldcs(base + (size_t)c * (HW/4));
        acc.x += w * x.x; acc.y += w * x.y; acc.z += w * x.z; acc.w += w * x.w;
    }
    d_gpart4[cb * (HW/4) + p4] = acc;
}

// ---------------------------------------------------------------------------
// Phase 1b: scatter, thread-per-point (proven r6 form).
// ---------------------------------------------------------------------------
template<int CF>
__device__ void scatter_level(const float* __restrict__ feat,
                              const float* __restrict__ coord,
                              const int* __restrict__ grid,
                              int N, const float* __restrict__ u,
                              int blockInLevel) {
    constexpr int L  = CF + 3;
    constexpr int NC = CF/4 + 1;
    __shared__ __align__(16) float4 suT[NC * 9];
    __syncthreads();
    for (int idx = threadIdx.x; idx < NC * 9 * 4; idx += blockDim.x) {
        int c = idx & 3, jt = idx >> 2;
        int t = jt % 9, j = jt / 9;
        int i = 4 * j + c;
        ((float*)&suT[j * 9 + t])[c] = (i < L) ? u[t * L + i] : 0.f;
    }
    __syncthreads();
    int n = blockInLevel * 256 + threadIdx.x;
    if (n >= N) return;
    float acc[9];
    #pragma unroll
    for (int t = 0; t < 9; ++t) acc[t] = 0.f;
    const float4* fp = (const float4*)(feat + (size_t)n * CF);
    #pragma unroll
    for (int j = 0; j < CF/4; ++j) {
        float4 p = __ldg(fp + j);
        #pragma unroll
        for (int t = 0; t < 9; ++t) {
            float4 w = suT[j * 9 + t];
            acc[t] += w.x*p.x + w.y*p.y + w.z*p.z + w.w*p.w;
        }
    }
    float c0 = __ldg(coord + n*3 + 0);
    float c1 = __ldg(coord + n*3 + 1);
    float c2 = __ldg(coord + n*3 + 2);
    #pragma unroll
    for (int t = 0; t < 9; ++t) {
        float4 w = suT[(CF/4) * 9 + t];
        acc[t] += w.x*c0 + w.y*c1 + w.z*c2;
    }
    int2 gxy = __ldg((const int2*)grid + n);   // (col, row)
    #pragma unroll
    for (int t = 0; t < 9; ++t) {
        int h = gxy.y - t/3 + 1;
        int w = gxy.x - t%3 + 1;
        if (h >= 0 && h < Hh && w >= 0 && w < Ww)
            atomicAdd(&d_spt[h * Ww + w], acc[t]);
    }
}

// ---------------------------------------------------------------------------
// Phase 2: att for one row h (176 active threads of 256).
// ---------------------------------------------------------------------------
__device__ void att_part(int h, const float* __restrict__ sp_b) {
    __shared__ __align__(16) float sm[3][712];   // cols at [4 .. 708)
    __shared__ float swg[9], sks[9];
    int t = threadIdx.x;
    __syncthreads();
    if (t < 9) {
        swg[t] = d_wg[t];
        int rc = t / 3, cc = t % 3;
        float s = 0.f;
        #pragma unroll
        for (int ty = 0; ty < 3; ++ty) {
            if ((rc == 0 && ty == 0) || (rc == 2 && ty == 2)) continue;
            #pragma unroll
            for (int tx = 0; tx < 3; ++tx) {
                if ((cc == 0 && tx == 0) || (cc == 2 && tx == 2)) continue;
                s += d_K[ty*3 + tx];
            }
        }
        sks[t] = s;
    }
    if (t < 176) {
        #pragma unroll
        for (int r = 0; r < 3; ++r) {
            int y = h + r - 1;
            float4 s = make_float4(0.f, 0.f, 0.f, 0.f);
            if (y >= 0 && y < Hh) {
                #pragma unroll
                for (int sl = 0; sl < 8; ++sl) {
                    float4 v = __ldg(&d_gpart4[sl * (HW/4) + y * W4 + t]);
                    s.x += v.x; s.y += v.y; s.z += v.z; s.w += v.w;
                }
            }
            *(float4*)&sm[r][4 + 4*t] = s;
            if (t == 0) { sm[r][3] = 0.f; sm[r][708] = 0.f; }
        }
    }
    __syncthreads();
    if (t < 176) {
        float bias = sp_b[0];
        int rc = (h == 0) ? 0 : (h == Hh-1 ? 2 : 1);
        float4 spt = ((const float4*)d_spt)[h * W4 + t];
        float sptv[4] = {spt.x, spt.y, spt.z, spt.w};
        float res[4];
        #pragma unroll
        for (int i = 0; i < 4; ++i) {
            int col = 4*t + i;
            int cc = (col == 0) ? 0 : (col == Ww-1 ? 2 : 1);
            float s = bias + sptv[i] + sks[rc*3 + cc];
            #pragma unroll
            for (int t9 = 0; t9 < 9; ++t9) {
                int dy = t9 / 3, dx = t9 % 3;
                s += swg[t9] * sm[dy][4 + col + dx - 1];
            }
            res[i] = 1.f / (1.f + __expf(-s));
        }
        d_att4[h * W4 + t] = make_float4(res[0], res[1], res[2], res[3]);
    }
}

// ---------------------------------------------------------------------------
// Phase 3: mul for virtual block vb (1408 = 176 pixel x 8 groups of 32ch).
// ---------------------------------------------------------------------------
__device__ void mul_part(const float* __restrict__ img, float* __restrict__ out,
                         int vb) {
    int pb = vb % 176, cb = vb / 176;
    int p4 = pb * 256 + threadIdx.x;
    float4 a = __ldg(&d_att4[p4]);
    size_t off = (size_t)cb * 32 * (HW/4) + p4;
    const float4* img4 = (const float4*)img;
    float4* out4 = (float4*)out;
    #pragma unroll
    for (int c = 0; c < 32; ++c) {
        float4 v = __ldcs(&img4[off + (size_t)c * (HW/4)]);
        float4 r = make_float4(v.x * a.x, v.y * a.y, v.z * a.z, v.w * a.w);
        __stcs(&out4[off + (size_t)c * (HW/4)], r);
    }
}

// ---------------------------------------------------------------------------
// Persistent mega-kernel: all phases, grid barriers between, one launch.
// ---------------------------------------------------------------------------
__global__ void __launch_bounds__(256, 4)
mega_kernel(const float* __restrict__ img, float* __restrict__ out,
            const float* __restrict__ f0, const float* __restrict__ c0,
            const int* __restrict__ g0, int N0,
            const float* __restrict__ f1, const float* __restrict__ c1,
            const int* __restrict__ g1, int N1,
            const float* __restrict__ f2, const float* __restrict__ c2,
            const int* __restrict__ g2, int N2,
            const float* __restrict__ rd0_w, const float* __restrict__ rd0_b,
            const float* __restrict__ rd1_w, const float* __restrict__ rd1_b,
            const float* __restrict__ rd2_w, const float* __restrict__ rd2_b,
            const float* __restrict__ rd3_w, const float* __restrict__ rd3_b,
            const float* __restrict__ sp_w,  const float* __restrict__ sp_b,
            int sb0, int sb1, int sb2) {
    int B = blockIdx.x;
    // ---- Phase 0: fold (9) + zero d_spt (176) ----
    for (int vb = B; vb < 9 + 176; vb += GRID_BLOCKS) {
        if (vb < 9) {
            fold_part(vb, sp_w, rd0_w, rd1_w, rd0_b, rd1_b, rd2_w, rd2_b, rd3_b);
        } else {
            ((float4*)d_spt)[(vb - 9) * 256 + threadIdx.x] =
                make_float4(0.f, 0.f, 0.f, 0.f);
        }
    }
    grid_sync();
    // ---- Phase 1: scatter (SB, first) + gated (1408) ----
    int SB = sb0 + sb1 + sb2;
    for (int vb = B; vb < SB + 1408; vb += GRID_BLOCKS) {
        if (vb < sb0) {
            scatter_level<32>(f0, c0, g0, N0, d_u0, vb);
        } else if (vb < sb0 + sb1) {
            scatter_level<64>(f1, c1, g1, N1, d_u1, vb - sb0);
        } else if (vb < SB) {
            scatter_level<128>(f2, c2, g2, N2, d_v2, vb - sb0 - sb1);
        } else {
            gated_part(img, rd3_w, vb - SB);
        }
    }
    grid_sync();
    // ---- Phase 2: att (256 rows) ----
    for (int vb = B; vb < Hh; vb += GRID_BLOCKS) att_part(vb, sp_b);
    grid_sync();
    // ---- Phase 3: mul (1408) ----
    for (int vb = B; vb < 1408; vb += GRID_BLOCKS) mul_part(img, out, vb);
}

extern "C" void kernel_launch(void* const* d_in, const int* in_sizes, int n_in,
                              void* d_out, int out_size) {
    const float* img   = (const float*)d_in[0];
    const float* f0    = (const float*)d_in[1];
    const float* c0    = (const float*)d_in[2];
    const int*   g0    = (const int*)  d_in[3];
    const float* f1    = (const float*)d_in[4];
    const float* c1    = (const float*)d_in[5];
    const int*   g1    = (const int*)  d_in[6];
    const float* f2    = (const float*)d_in[7];
    const float* c2    = (const float*)d_in[8];
    const int*   g2    = (const int*)  d_in[9];
    const float* rd0_w = (const float*)d_in[10];
    const float* rd0_b = (const float*)d_in[11];
    const float* rd1_w = (const float*)d_in[12];
    const float* rd1_b = (const float*)d_in[13];
    const float* rd2_w = (const float*)d_in[14];
    const float* rd2_b = (const float*)d_in[15];
    const float* rd3_w = (const float*)d_in[16];
    const float* rd3_b = (const float*)d_in[17];
    const float* sp_w  = (const float*)d_in[18];
    const float* sp_b  = (const float*)d_in[19];

    int N0 = in_sizes[1] / 32;
    int N1 = in_sizes[4] / 64;
    int N2 = in_sizes[7] / 128;
    int sb0 = (N0 + 255) / 256;
    int sb1 = (N1 + 255) / 256;
    int sb2 = (N2 + 255) / 256;

    mega_kernel<<<GRID_BLOCKS, 256>>>(img, (float*)d_out,
                                      f0, c0, g0, N0,
                                      f1, c1, g1, N1,
                                      f2, c2, g2, N2,
                                      rd0_w, rd0_b, rd1_w, rd1_b,
                                      rd2_w, rd2_b, rd3_w, rd3_b,
                                      sp_w, sp_b, sb0, sb1, sb2);
}